// round 9
// baseline (speedup 1.0000x reference)
#include <cuda_runtime.h>
#include <math.h>

#define N_ATOMS 10000
#define N_EDGES 160000
#define NSPEC   8
#define NSTRUCT 8
#define CH      16
#define NMAX    4
#define NBASIS  8
#define LMAXV   3
#define KTOT    256
#define CUTOFF  5.0f
#define PI_F    3.14159265358979f

// ---------------- device scratch ----------------
__device__ float  g_sh[(size_t)N_EDGES * 16];   // CSR order
__device__ float  g_R [(size_t)N_EDGES * 16];   // CSR order (l,n)
__device__ int    g_send[N_EDGES];              // sender per CSR slot
__device__ int    g_rank[N_EDGES];              // edge -> rank within receiver segment
__device__ float  g_cemb[N_ATOMS * CH];
__device__ float  g_h1[N_ATOMS * CH];
__device__ float4 g_pos4[N_ATOMS];
__device__ float  g_WT[CH * KTOT];              // W_inv1 transposed [c][jj]
__device__ int    g_deg[N_ATOMS];               // zero at entry of every launch (see k_scan)
__device__ int    g_off[N_ATOMS + 1];

// ---------------- prep: cemb, pos4, W^T, hist+rank, out zero (one pass) ----------------
__global__ void k_prep(const float* __restrict__ embed, const int* __restrict__ species,
                       const float* __restrict__ pos, const float* __restrict__ W_inv1,
                       const int* __restrict__ recv, float* __restrict__ out) {
    int i = blockIdx.x * blockDim.x + threadIdx.x;
    if (i < N_EDGES) {
        g_rank[i] = atomicAdd(&g_deg[recv[i]], 1);
        g_cemb[i] = embed[species[i >> 4] * CH + (i & 15)];   // N_ATOMS*CH == N_EDGES
    }
    if (i < N_ATOMS)
        g_pos4[i] = make_float4(pos[3 * i], pos[3 * i + 1], pos[3 * i + 2], 0.f);
    if (i < KTOT * CH)
        g_WT[(i & 15) * KTOT + (i >> 4)] = W_inv1[i];
    if (i < NSTRUCT) out[i] = 0.f;
}

// ---------------- exclusive scan; writes sentinel; re-zeroes g_deg ----------------
__global__ void __launch_bounds__(1024) k_scan() {
    const int CHUNK = 10;
    int t = threadIdx.x;
    int lane = t & 31, warp = t >> 5;
    int start = t * CHUNK;

    int v[CHUNK];
    int s = 0;
#pragma unroll
    for (int i = 0; i < CHUNK; i++) {
        int idx = start + i;
        v[i] = (idx < N_ATOMS) ? g_deg[idx] : 0;
        s += v[i];
    }
    int x = s;
#pragma unroll
    for (int o = 1; o < 32; o <<= 1) {
        int y = __shfl_up_sync(0xFFFFFFFFu, x, o);
        if (lane >= o) x += y;
    }
    __shared__ int ws[32];
    if (lane == 31) ws[warp] = x;
    __syncthreads();
    if (warp == 0) {
        int wv = ws[lane];
#pragma unroll
        for (int o = 1; o < 32; o <<= 1) {
            int y = __shfl_up_sync(0xFFFFFFFFu, wv, o);
            if (lane >= o) wv += y;
        }
        ws[lane] = wv;
    }
    __syncthreads();
    int run = x - s + ((warp > 0) ? ws[warp - 1] : 0);
#pragma unroll
    for (int i = 0; i < CHUNK; i++) {
        int idx = start + i;
        if (idx < N_ATOMS) { g_off[idx] = run; g_deg[idx] = 0; }  // zero for next call
        run += v[i];
    }
    if (t == 0) g_off[N_ATOMS] = N_EDGES;   // sentinel
}

// ---------------- per-edge: sh[16] + R[16] written at CSR slot ----------------
__global__ void k_edges(const int* __restrict__ senders,
                        const int* __restrict__ recv,
                        const float* __restrict__ W_rad) {
    __shared__ float wrad[(LMAXV + 1) * NBASIS * NMAX];
    if (threadIdx.x < (LMAXV + 1) * NBASIS * NMAX) wrad[threadIdx.x] = W_rad[threadIdx.x];
    __syncthreads();

    int e = blockIdx.x * blockDim.x + threadIdx.x;
    if (e >= N_EDGES) return;
    int s = senders[e], r = recv[e];
    int posn = g_off[r] + g_rank[e];
    float4 ps = g_pos4[s];
    float4 pr = g_pos4[r];
    float dx = pr.x - ps.x, dy = pr.y - ps.y, dz = pr.z - ps.z;
    float rn = sqrtf(dx * dx + dy * dy + dz * dz);
    float inv_u = __frcp_rn(fmaxf(rn, 1e-6f));
    float x = dx * inv_u, y = dy * inv_u, z = dz * inv_u;
    float x2 = x * x, y2 = y * y, z2 = z * z;

    float sh[16];
    sh[0]  = 0.28209479f;
    sh[1]  = 0.48860251f * y;
    sh[2]  = 0.48860251f * z;
    sh[3]  = 0.48860251f * x;
    sh[4]  = 1.09254843f * x * y;
    sh[5]  = 1.09254843f * y * z;
    sh[6]  = 0.31539157f * (3.0f * z2 - 1.0f);
    sh[7]  = 1.09254843f * x * z;
    sh[8]  = 0.54627422f * (x2 - y2);
    sh[9]  = 0.59004359f * y * (3.0f * x2 - y2);
    sh[10] = 2.89061144f * x * y * z;
    sh[11] = 0.45704579f * y * (5.0f * z2 - 1.0f);
    sh[12] = 0.37317633f * z * (5.0f * z2 - 3.0f);
    sh[13] = 0.45704579f * x * (5.0f * z2 - 1.0f);
    sh[14] = 1.44530572f * z * (x2 - y2);
    sh[15] = 0.59004359f * x * (x2 - 3.0f * y2);

    // accurate sincos once, stable rotation recurrence
    float rr = fmaxf(rn, 1e-6f);
    float theta = PI_F * (1.0f / CUTOFF) * rr;
    float s1, c1;
    sincosf(theta, &s1, &c1);
    float fc = (theta < PI_F) ? 0.5f * (c1 + 1.0f) : 0.0f;
    float pref = 0.63245553f * inv_u * fc;
    float bf[NBASIS];
    {
        float sk = s1, ck = c1;
        bf[0] = pref * sk;
#pragma unroll
        for (int n = 1; n < NBASIS; n++) {
            float sn = fmaf(sk, c1, ck * s1);
            float cn = fmaf(ck, c1, -sk * s1);
            sk = sn; ck = cn;
            bf[n] = pref * sk;
        }
    }

    float4 Rq[LMAXV + 1];
#pragma unroll
    for (int l = 0; l <= LMAXV; l++) {
        float a0 = 0.f, a1 = 0.f, a2 = 0.f, a3 = 0.f;
#pragma unroll
        for (int b = 0; b < NBASIS; b++) {
            const float* wl = &wrad[l * (NBASIS * NMAX) + b * NMAX];
            a0 = fmaf(bf[b], wl[0], a0);
            a1 = fmaf(bf[b], wl[1], a1);
            a2 = fmaf(bf[b], wl[2], a2);
            a3 = fmaf(bf[b], wl[3], a3);
        }
        Rq[l] = make_float4(a0, a1, a2, a3);
    }

    g_send[posn] = s;
    float4* SH4 = (float4*)&g_sh[(size_t)posn * 16];
    SH4[0] = make_float4(sh[0],  sh[1],  sh[2],  sh[3]);
    SH4[1] = make_float4(sh[4],  sh[5],  sh[6],  sh[7]);
    SH4[2] = make_float4(sh[8],  sh[9],  sh[10], sh[11]);
    SH4[3] = make_float4(sh[12], sh[13], sh[14], sh[15]);
    float4* R4p = (float4*)&g_R[(size_t)posn * 16];
    R4p[0] = Rq[0]; R4p[1] = Rq[1]; R4p[2] = Rq[2]; R4p[3] = Rq[3];
}

// ---------------- warp-per-atom layer: gather + CG invariants ----------------
template<bool FINAL>
__global__ void __launch_bounds__(128) k_layer(
    int use_h1,
    const float* __restrict__ w_out,   // final only
    const float* __restrict__ comp_w,  // final only
    const int* __restrict__ species,   // final only
    const int* __restrict__ sid,       // final only
    float* __restrict__ out)           // final only
{
    const float* __restrict__ h_in = use_h1 ? g_h1 : g_cemb;
    int warp = threadIdx.x >> 5, lane = threadIdx.x & 31;
    int atom = (blockIdx.x << 2) + warp;
    int jg = lane & 15, ch2 = (lane >> 4) << 1;
    int l = (jg == 0) ? 0 : (jg < 4) ? 1 : (jg < 9) ? 2 : 3;

    __shared__ float  smA[4][16 * 4 * 17];
    __shared__ float4 sminv4[4][KTOT / 4];
    __shared__ int    bsid[4];
    __shared__ float  bval[4];

    int off = g_off[atom];
    int cnt = g_off[atom + 1] - off;

    float acc[4][8];
#pragma unroll
    for (int n = 0; n < 4; n++)
#pragma unroll
        for (int cc = 0; cc < 8; cc++) acc[n][cc] = 0.f;

    const float* shp = g_sh + (size_t)off * 16 + jg;
    const float* Rp  = g_R  + (size_t)off * 16 + 4 * l;
    const int*   sp  = g_send + off;
    const float4* h4 = (const float4*)h_in;

#define ACCROW(n, u, ha, hb) \
        acc[n][0] = fmaf(u, ha.x, acc[n][0]); acc[n][1] = fmaf(u, ha.y, acc[n][1]); \
        acc[n][2] = fmaf(u, ha.z, acc[n][2]); acc[n][3] = fmaf(u, ha.w, acc[n][3]); \
        acc[n][4] = fmaf(u, hb.x, acc[n][4]); acc[n][5] = fmaf(u, hb.y, acc[n][5]); \
        acc[n][6] = fmaf(u, hb.z, acc[n][6]); acc[n][7] = fmaf(u, hb.w, acc[n][7]);

    int s0 = (cnt > 0) ? sp[0] : 0;
    int s1 = (cnt > 1) ? sp[1] : 0;
    int k = 0;
    for (; k + 1 < cnt; k += 2) {
        float  shv0 = shp[(size_t)k * 16];
        float  shv1 = shp[(size_t)(k + 1) * 16];
        float4 R40  = *(const float4*)(Rp + (size_t)k * 16);
        float4 R41  = *(const float4*)(Rp + (size_t)(k + 1) * 16);
        float4 ha0  = h4[s0 * 4 + ch2];
        float4 hb0  = h4[s0 * 4 + ch2 + 1];
        float4 ha1  = h4[s1 * 4 + ch2];
        float4 hb1  = h4[s1 * 4 + ch2 + 1];
        if (k + 2 < cnt) s0 = sp[k + 2];
        if (k + 3 < cnt) s1 = sp[k + 3];

        float u0 = shv0 * R40.x, u1 = shv0 * R40.y, u2 = shv0 * R40.z, u3 = shv0 * R40.w;
        ACCROW(0, u0, ha0, hb0) ACCROW(1, u1, ha0, hb0)
        ACCROW(2, u2, ha0, hb0) ACCROW(3, u3, ha0, hb0)
        float v0 = shv1 * R41.x, v1 = shv1 * R41.y, v2 = shv1 * R41.z, v3 = shv1 * R41.w;
        ACCROW(0, v0, ha1, hb1) ACCROW(1, v1, ha1, hb1)
        ACCROW(2, v2, ha1, hb1) ACCROW(3, v3, ha1, hb1)
    }
    if (k < cnt) {
        float  shv = shp[(size_t)k * 16];
        float4 R4  = *(const float4*)(Rp + (size_t)k * 16);
        float4 ha  = h4[s0 * 4 + ch2];
        float4 hb  = h4[s0 * 4 + ch2 + 1];
        float u0 = shv * R4.x, u1 = shv * R4.y, u2 = shv * R4.z, u3 = shv * R4.w;
        ACCROW(0, u0, ha, hb) ACCROW(1, u1, ha, hb)
        ACCROW(2, u2, ha, hb) ACCROW(3, u3, ha, hb)
    }
#undef ACCROW

    // write squared A to warp-private smem
    float* sA = smA[warp];
#pragma unroll
    for (int n = 0; n < 4; n++)
#pragma unroll
        for (int cc = 0; cc < 8; cc++) {
            float a = acc[n][cc];
            sA[(jg * 4 + n) * 17 + 4 * ch2 + cc] = a * a;
        }
    __syncwarp();

    float inv[8];
#pragma unroll
    for (int q = 0; q < 8; q++) {
        int idx = lane * 8 + q;
        int li = idx >> 6, ni = (idx >> 4) & 3, ci = idx & 15;
        int base = li * li;
        float sacc = 0.f;
        for (int m = 0; m <= 2 * li; m++)
            sacc += sA[((base + m) * 4 + ni) * 17 + ci];
        inv[q] = sacc * rsqrtf(2.0f * (float)li + 1.0f);
    }

    if (FINAL) {
        float part = 0.f;
#pragma unroll
        for (int q = 0; q < 8; q++)
            part = fmaf(inv[q], w_out[lane * 8 + q], part);
#pragma unroll
        for (int o = 16; o > 0; o >>= 1)
            part += __shfl_down_sync(0xFFFFFFFFu, part, o);
        if (lane == 0) {
            bsid[warp] = sid[atom];
            bval[warp] = part + comp_w[species[atom]];
        }
        __syncthreads();
        if (threadIdx.x == 0) {   // sorted structure_ids -> usually 1 atomic per block
            int cur = bsid[0]; float a = bval[0];
#pragma unroll
            for (int w = 1; w < 4; w++) {
                if (bsid[w] == cur) a += bval[w];
                else { atomicAdd(&out[cur], a); cur = bsid[w]; a = bval[w]; }
            }
            atomicAdd(&out[cur], a);
        }
    } else {
        float4* sv4 = sminv4[warp];
#pragma unroll
        for (int q = 0; q < 8; q += 4)
            sv4[(lane * 8 + q) >> 2] = make_float4(inv[q], inv[q + 1], inv[q + 2], inv[q + 3]);
        __syncwarp();
        int cp = lane & 15, half = lane >> 4;
        const float4* WT4 = (const float4*)(g_WT + cp * KTOT + half * 128);
        const float4* svh = sv4 + half * 32;
        float p = 0.f;
#pragma unroll
        for (int i = 0; i < 32; i++) {
            float4 iv = svh[i];
            float4 wt = WT4[i];
            p = fmaf(iv.x, wt.x, p);
            p = fmaf(iv.y, wt.y, p);
            p = fmaf(iv.z, wt.z, p);
            p = fmaf(iv.w, wt.w, p);
        }
        p += __shfl_down_sync(0xFFFFFFFFu, p, 16);
        if (lane < 16)
            g_h1[atom * CH + lane] = p * g_cemb[atom * CH + lane];
    }
}

// ---------------- launch ----------------
extern "C" void kernel_launch(void* const* d_in, const int* in_sizes, int n_in,
                              void* d_out, int out_size) {
    const float* positions  = (const float*)d_in[0];
    const float* embed      = (const float*)d_in[1];
    const float* W_rad      = (const float*)d_in[2];
    const float* W_inv1     = (const float*)d_in[3];
    // d_in[4] = W_inv2 is dead: reference returns inv2 before applying it
    const float* w_out      = (const float*)d_in[5];
    const float* comp_w     = (const float*)d_in[6];
    const int*   senders    = (const int*)d_in[7];
    const int*   receivers  = (const int*)d_in[8];
    const int*   species    = (const int*)d_in[9];
    const int*   struct_ids = (const int*)d_in[10];
    float* out = (float*)d_out;

    k_prep<<<(N_EDGES + 255) / 256, 256>>>(embed, species, positions, W_inv1, receivers, out);
    k_scan<<<1, 1024>>>();
    k_edges<<<(N_EDGES + 255) / 256, 256>>>(senders, receivers, W_rad);

    k_layer<false><<<N_ATOMS / 4, 128>>>(0, nullptr, nullptr, nullptr, nullptr, nullptr);
    k_layer<true><<<N_ATOMS / 4, 128>>>(1, w_out, comp_w, species, struct_ids, out);
}

// round 12
// speedup vs baseline: 1.4192x; 1.4192x over previous
#include <cuda_runtime.h>
#include <math.h>

#define N_ATOMS 10000
#define N_EDGES 160000
#define NSPEC   8
#define NSTRUCT 8
#define CH      16
#define NMAX    4
#define NBASIS  8
#define LMAXV   3
#define KTOT    256
#define CUTOFF  5.0f
#define PI_F    3.14159265358979f

// ---------------- device scratch ----------------
__device__ float  g_sh[(size_t)N_EDGES * 16];   // CSR order
__device__ float  g_R [(size_t)N_EDGES * 16];   // CSR order (l,n)
__device__ int    g_send[N_EDGES];              // sender per CSR slot
__device__ int    g_rank[N_EDGES];              // edge -> rank within receiver segment
__device__ float  g_cemb[N_ATOMS * CH];
__device__ float  g_h1[N_ATOMS * CH];
__device__ float4 g_pos4[N_ATOMS];
__device__ float  g_wp[KTOT];                   // w_out[l,n,c] * rsqrt(2l+1)
__device__ int    g_deg[N_ATOMS];               // zero at entry (re-zeroed by k_scan)
__device__ int    g_off[N_ATOMS + 1];

// ---------------- prep: cemb, pos4, w', hist+rank, out zero (one pass) ----------------
__global__ void k_prep(const float* __restrict__ embed, const int* __restrict__ species,
                       const float* __restrict__ pos, const float* __restrict__ w_out,
                       const int* __restrict__ recv, float* __restrict__ out) {
    int i = blockIdx.x * blockDim.x + threadIdx.x;
    if (i < N_EDGES) {
        g_rank[i] = atomicAdd(&g_deg[recv[i]], 1);
        g_cemb[i] = embed[species[i >> 4] * CH + (i & 15)];   // N_ATOMS*CH == N_EDGES
    }
    if (i < N_ATOMS)
        g_pos4[i] = make_float4(pos[3 * i], pos[3 * i + 1], pos[3 * i + 2], 0.f);
    if (i < KTOT) {
        int l = i >> 6;
        g_wp[i] = w_out[i] * rsqrtf(2.0f * (float)l + 1.0f);
    }
    if (i < NSTRUCT) out[i] = 0.f;
}

// ---------------- exclusive scan; writes sentinel; re-zeroes g_deg ----------------
__global__ void __launch_bounds__(1024) k_scan() {
    const int CHUNK = 10;
    int t = threadIdx.x;
    int lane = t & 31, warp = t >> 5;
    int start = t * CHUNK;

    int v[CHUNK];
    int s = 0;
#pragma unroll
    for (int i = 0; i < CHUNK; i++) {
        int idx = start + i;
        v[i] = (idx < N_ATOMS) ? g_deg[idx] : 0;
        s += v[i];
    }
    int x = s;
#pragma unroll
    for (int o = 1; o < 32; o <<= 1) {
        int y = __shfl_up_sync(0xFFFFFFFFu, x, o);
        if (lane >= o) x += y;
    }
    __shared__ int ws[32];
    if (lane == 31) ws[warp] = x;
    __syncthreads();
    if (warp == 0) {
        int wv = ws[lane];
#pragma unroll
        for (int o = 1; o < 32; o <<= 1) {
            int y = __shfl_up_sync(0xFFFFFFFFu, wv, o);
            if (lane >= o) wv += y;
        }
        ws[lane] = wv;
    }
    __syncthreads();
    int run = x - s + ((warp > 0) ? ws[warp - 1] : 0);
#pragma unroll
    for (int i = 0; i < CHUNK; i++) {
        int idx = start + i;
        if (idx < N_ATOMS) { g_off[idx] = run; g_deg[idx] = 0; }
        run += v[i];
    }
    if (t == 0) g_off[N_ATOMS] = N_EDGES;
}

// ---------------- per-edge: sh[16] + R[16] written at CSR slot ----------------
__global__ void k_edges(const int* __restrict__ senders,
                        const int* __restrict__ recv,
                        const float* __restrict__ W_rad) {
    __shared__ float wrad[(LMAXV + 1) * NBASIS * NMAX];
    if (threadIdx.x < (LMAXV + 1) * NBASIS * NMAX) wrad[threadIdx.x] = W_rad[threadIdx.x];
    __syncthreads();

    int e = blockIdx.x * blockDim.x + threadIdx.x;
    if (e >= N_EDGES) return;
    int s = senders[e], r = recv[e];
    int posn = g_off[r] + g_rank[e];
    float4 ps = g_pos4[s];
    float4 pr = g_pos4[r];
    float dx = pr.x - ps.x, dy = pr.y - ps.y, dz = pr.z - ps.z;
    float rn = sqrtf(dx * dx + dy * dy + dz * dz);
    float inv_u = __frcp_rn(fmaxf(rn, 1e-6f));
    float x = dx * inv_u, y = dy * inv_u, z = dz * inv_u;
    float x2 = x * x, y2 = y * y, z2 = z * z;

    float sh[16];
    sh[0]  = 0.28209479f;
    sh[1]  = 0.48860251f * y;
    sh[2]  = 0.48860251f * z;
    sh[3]  = 0.48860251f * x;
    sh[4]  = 1.09254843f * x * y;
    sh[5]  = 1.09254843f * y * z;
    sh[6]  = 0.31539157f * (3.0f * z2 - 1.0f);
    sh[7]  = 1.09254843f * x * z;
    sh[8]  = 0.54627422f * (x2 - y2);
    sh[9]  = 0.59004359f * y * (3.0f * x2 - y2);
    sh[10] = 2.89061144f * x * y * z;
    sh[11] = 0.45704579f * y * (5.0f * z2 - 1.0f);
    sh[12] = 0.37317633f * z * (5.0f * z2 - 3.0f);
    sh[13] = 0.45704579f * x * (5.0f * z2 - 1.0f);
    sh[14] = 1.44530572f * z * (x2 - y2);
    sh[15] = 0.59004359f * x * (x2 - 3.0f * y2);

    float rr = fmaxf(rn, 1e-6f);
    float theta = PI_F * (1.0f / CUTOFF) * rr;
    float s1, c1;
    sincosf(theta, &s1, &c1);
    float fc = (theta < PI_F) ? 0.5f * (c1 + 1.0f) : 0.0f;
    float pref = 0.63245553f * inv_u * fc;
    float bf[NBASIS];
    {
        float sk = s1, ck = c1;
        bf[0] = pref * sk;
#pragma unroll
        for (int n = 1; n < NBASIS; n++) {
            float sn = fmaf(sk, c1, ck * s1);
            float cn = fmaf(ck, c1, -sk * s1);
            sk = sn; ck = cn;
            bf[n] = pref * sk;
        }
    }

    float4 Rq[LMAXV + 1];
#pragma unroll
    for (int l = 0; l <= LMAXV; l++) {
        float a0 = 0.f, a1 = 0.f, a2 = 0.f, a3 = 0.f;
#pragma unroll
        for (int b = 0; b < NBASIS; b++) {
            const float* wl = &wrad[l * (NBASIS * NMAX) + b * NMAX];
            a0 = fmaf(bf[b], wl[0], a0);
            a1 = fmaf(bf[b], wl[1], a1);
            a2 = fmaf(bf[b], wl[2], a2);
            a3 = fmaf(bf[b], wl[3], a3);
        }
        Rq[l] = make_float4(a0, a1, a2, a3);
    }

    g_send[posn] = s;
    float4* SH4 = (float4*)&g_sh[(size_t)posn * 16];
    SH4[0] = make_float4(sh[0],  sh[1],  sh[2],  sh[3]);
    SH4[1] = make_float4(sh[4],  sh[5],  sh[6],  sh[7]);
    SH4[2] = make_float4(sh[8],  sh[9],  sh[10], sh[11]);
    SH4[3] = make_float4(sh[12], sh[13], sh[14], sh[15]);
    float4* R4p = (float4*)&g_R[(size_t)posn * 16];
    R4p[0] = Rq[0]; R4p[1] = Rq[1]; R4p[2] = Rq[2]; R4p[3] = Rq[3];
}

// ---------------- warp-per-atom layer: gather + CG invariants ----------------
// lane (jg = lane&15 owns j = l(jg)^2+m flat index; ch = lane>>4 owns c = 8ch..8ch+7)
template<bool FINAL>
__global__ void __launch_bounds__(128) k_layer(
    int use_h1,
    const float* __restrict__ W,       // W_inv1 (non-final)
    const float* __restrict__ comp_w,  // final
    const int* __restrict__ species,   // final
    const int* __restrict__ sid,       // final
    float* __restrict__ out)           // final
{
    const float* __restrict__ h_in = use_h1 ? g_h1 : g_cemb;
    int warp = threadIdx.x >> 5, lane = threadIdx.x & 31;
    int atom = (blockIdx.x << 2) + warp;
    int jg = lane & 15, ch2 = (lane >> 4) << 1;
    int l = (jg == 0) ? 0 : (jg < 4) ? 1 : (jg < 9) ? 2 : 3;

    int off = g_off[atom];
    int cnt = g_off[atom + 1] - off;

    float acc[4][8];
#pragma unroll
    for (int n = 0; n < 4; n++)
#pragma unroll
        for (int cc = 0; cc < 8; cc++) acc[n][cc] = 0.f;

    const float* shp = g_sh + (size_t)off * 16 + jg;
    const float* Rp  = g_R  + (size_t)off * 16 + 4 * l;
    const int*   sp  = g_send + off;
    const float4* h4 = (const float4*)h_in;

#define ACCROW(n, u, ha, hb) \
        acc[n][0] = fmaf(u, ha.x, acc[n][0]); acc[n][1] = fmaf(u, ha.y, acc[n][1]); \
        acc[n][2] = fmaf(u, ha.z, acc[n][2]); acc[n][3] = fmaf(u, ha.w, acc[n][3]); \
        acc[n][4] = fmaf(u, hb.x, acc[n][4]); acc[n][5] = fmaf(u, hb.y, acc[n][5]); \
        acc[n][6] = fmaf(u, hb.z, acc[n][6]); acc[n][7] = fmaf(u, hb.w, acc[n][7]);

    int s0 = (cnt > 0) ? sp[0] : 0;
    int s1 = (cnt > 1) ? sp[1] : 0;
    int k = 0;
    for (; k + 1 < cnt; k += 2) {
        float  shv0 = shp[(size_t)k * 16];
        float  shv1 = shp[(size_t)(k + 1) * 16];
        float4 R40  = *(const float4*)(Rp + (size_t)k * 16);
        float4 R41  = *(const float4*)(Rp + (size_t)(k + 1) * 16);
        float4 ha0  = h4[s0 * 4 + ch2];
        float4 hb0  = h4[s0 * 4 + ch2 + 1];
        float4 ha1  = h4[s1 * 4 + ch2];
        float4 hb1  = h4[s1 * 4 + ch2 + 1];
        if (k + 2 < cnt) s0 = sp[k + 2];
        if (k + 3 < cnt) s1 = sp[k + 3];

        float u0 = shv0 * R40.x, u1 = shv0 * R40.y, u2 = shv0 * R40.z, u3 = shv0 * R40.w;
        ACCROW(0, u0, ha0, hb0) ACCROW(1, u1, ha0, hb0)
        ACCROW(2, u2, ha0, hb0) ACCROW(3, u3, ha0, hb0)
        float v0 = shv1 * R41.x, v1 = shv1 * R41.y, v2 = shv1 * R41.z, v3 = shv1 * R41.w;
        ACCROW(0, v0, ha1, hb1) ACCROW(1, v1, ha1, hb1)
        ACCROW(2, v2, ha1, hb1) ACCROW(3, v3, ha1, hb1)
    }
    if (k < cnt) {
        float  shv = shp[(size_t)k * 16];
        float4 R4  = *(const float4*)(Rp + (size_t)k * 16);
        float4 ha  = h4[s0 * 4 + ch2];
        float4 hb  = h4[s0 * 4 + ch2 + 1];
        float u0 = shv * R4.x, u1 = shv * R4.y, u2 = shv * R4.z, u3 = shv * R4.w;
        ACCROW(0, u0, ha, hb) ACCROW(1, u1, ha, hb)
        ACCROW(2, u2, ha, hb) ACCROW(3, u3, ha, hb)
    }
#undef ACCROW

    if (FINAL) {
        // fold w' into A^2 directly: e = sum_{j,c} A[j,c]^2 * w'[l,n,c]; all in registers
        const float* wp = g_wp + l * 64 + 4 * ch2;   // + n*16 + cc
        float part = 0.f;
#pragma unroll
        for (int n = 0; n < 4; n++) {
            const float* wn = wp + n * 16;
#pragma unroll
            for (int cc = 0; cc < 8; cc++) {
                float a = acc[n][cc];
                part = fmaf(a * a, wn[cc], part);
            }
        }
#pragma unroll
        for (int o = 16; o > 0; o >>= 1)
            part += __shfl_down_sync(0xFFFFFFFFu, part, o);
        if (lane == 0)
            atomicAdd(&out[sid[atom]], part + comp_w[species[atom]]);
    } else {
        __shared__ float smA[4][16 * 4 * 17];
        __shared__ float sminv[4][KTOT];
        // write squared A to warp-private smem
        float* sA = smA[warp];
#pragma unroll
        for (int n = 0; n < 4; n++)
#pragma unroll
            for (int cc = 0; cc < 8; cc++) {
                float a = acc[n][cc];
                sA[(jg * 4 + n) * 17 + 4 * ch2 + cc] = a * a;
            }
        __syncwarp();

        float inv[8];
#pragma unroll
        for (int q = 0; q < 8; q++) {
            int idx = lane * 8 + q;
            int li = idx >> 6, ni = (idx >> 4) & 3, ci = idx & 15;
            int base = li * li;
            float sacc = 0.f;
            for (int m = 0; m <= 2 * li; m++)
                sacc += sA[((base + m) * 4 + ni) * 17 + ci];
            inv[q] = sacc * rsqrtf(2.0f * (float)li + 1.0f);
        }

        float* sv = sminv[warp];
#pragma unroll
        for (int q = 0; q < 8; q++) sv[lane * 8 + q] = inv[q];
        __syncwarp();
        int cp = lane & 15, half = lane >> 4;
        float p0 = 0.f, p1 = 0.f;
#pragma unroll 8
        for (int i = 0; i < 128; i += 2) {
            int jj = (half << 7) + i;
            p0 = fmaf(sv[jj],     W[jj * 16 + cp],       p0);
            p1 = fmaf(sv[jj + 1], W[(jj + 1) * 16 + cp], p1);
        }
        float p = p0 + p1;
        p += __shfl_down_sync(0xFFFFFFFFu, p, 16);
        if (lane < 16)
            g_h1[atom * CH + lane] = p * g_cemb[atom * CH + lane];
    }
}

// ---------------- launch ----------------
extern "C" void kernel_launch(void* const* d_in, const int* in_sizes, int n_in,
                              void* d_out, int out_size) {
    const float* positions  = (const float*)d_in[0];
    const float* embed      = (const float*)d_in[1];
    const float* W_rad      = (const float*)d_in[2];
    const float* W_inv1     = (const float*)d_in[3];
    // d_in[4] = W_inv2 is dead: reference returns inv2 before applying it
    const float* w_out      = (const float*)d_in[5];
    const float* comp_w     = (const float*)d_in[6];
    const int*   senders    = (const int*)d_in[7];
    const int*   receivers  = (const int*)d_in[8];
    const int*   species    = (const int*)d_in[9];
    const int*   struct_ids = (const int*)d_in[10];
    float* out = (float*)d_out;

    k_prep<<<(N_EDGES + 255) / 256, 256>>>(embed, species, positions, w_out, receivers, out);
    k_scan<<<1, 1024>>>();
    k_edges<<<(N_EDGES + 255) / 256, 256>>>(senders, receivers, W_rad);

    k_layer<false><<<N_ATOMS / 4, 128>>>(0, W_inv1, nullptr, nullptr, nullptr, nullptr);
    k_layer<true><<<N_ATOMS / 4, 128>>>(1, nullptr, comp_w, species, struct_ids, out);
}

// round 13
// speedup vs baseline: 1.4332x; 1.0099x over previous
#include <cuda_runtime.h>
#include <math.h>

#define N_ATOMS 10000
#define N_EDGES 160000
#define NSPEC   8
#define NSTRUCT 8
#define CH      16
#define NMAX    4
#define NBASIS  8
#define LMAXV   3
#define KTOT    256
#define CUTOFF  5.0f
#define PI_F    3.14159265358979f

// ---------------- device scratch ----------------
__device__ float  g_sh[(size_t)N_EDGES * 16];   // CSR order
__device__ float  g_R [(size_t)N_EDGES * 16];   // CSR order (l,n)
__device__ int    g_send[N_EDGES];              // sender per CSR slot
__device__ int    g_rank[N_EDGES];              // edge -> rank within receiver segment
__device__ float  g_cemb[N_ATOMS * CH];
__device__ float  g_h1[N_ATOMS * CH];
__device__ float4 g_pos4[N_ATOMS];
__device__ float  g_wp[KTOT];                   // w_out[l,n,c] * rsqrt(2l+1)
__device__ int    g_deg[N_ATOMS];               // zero at entry (re-zeroed by k_scan)
__device__ int    g_off[N_ATOMS + 1];

// ---------------- prep: cemb, pos4, w', hist+rank, out zero (one pass) ----------------
__global__ void k_prep(const float* __restrict__ embed, const int* __restrict__ species,
                       const float* __restrict__ pos, const float* __restrict__ w_out,
                       const int* __restrict__ recv, float* __restrict__ out) {
    int i = blockIdx.x * blockDim.x + threadIdx.x;
    if (i < N_EDGES) {
        g_rank[i] = atomicAdd(&g_deg[recv[i]], 1);
        g_cemb[i] = embed[species[i >> 4] * CH + (i & 15)];   // N_ATOMS*CH == N_EDGES
    }
    if (i < N_ATOMS)
        g_pos4[i] = make_float4(pos[3 * i], pos[3 * i + 1], pos[3 * i + 2], 0.f);
    if (i < KTOT) {
        int l = i >> 6;
        g_wp[i] = w_out[i] * rsqrtf(2.0f * (float)l + 1.0f);
    }
    if (i < NSTRUCT) out[i] = 0.f;
}

// ---------------- exclusive scan; writes sentinel; re-zeroes g_deg ----------------
__global__ void __launch_bounds__(1024) k_scan() {
    const int CHUNK = 10;
    int t = threadIdx.x;
    int lane = t & 31, warp = t >> 5;
    int start = t * CHUNK;

    int v[CHUNK];
    int s = 0;
#pragma unroll
    for (int i = 0; i < CHUNK; i++) {
        int idx = start + i;
        v[i] = (idx < N_ATOMS) ? g_deg[idx] : 0;
        s += v[i];
    }
    int x = s;
#pragma unroll
    for (int o = 1; o < 32; o <<= 1) {
        int y = __shfl_up_sync(0xFFFFFFFFu, x, o);
        if (lane >= o) x += y;
    }
    __shared__ int ws[32];
    if (lane == 31) ws[warp] = x;
    __syncthreads();
    if (warp == 0) {
        int wv = ws[lane];
#pragma unroll
        for (int o = 1; o < 32; o <<= 1) {
            int y = __shfl_up_sync(0xFFFFFFFFu, wv, o);
            if (lane >= o) wv += y;
        }
        ws[lane] = wv;
    }
    __syncthreads();
    int run = x - s + ((warp > 0) ? ws[warp - 1] : 0);
#pragma unroll
    for (int i = 0; i < CHUNK; i++) {
        int idx = start + i;
        if (idx < N_ATOMS) { g_off[idx] = run; g_deg[idx] = 0; }
        run += v[i];
    }
    if (t == 0) g_off[N_ATOMS] = N_EDGES;
}

// ---------------- per-edge: sh[16] + R[16] written at CSR slot ----------------
__global__ void k_edges(const int* __restrict__ senders,
                        const int* __restrict__ recv,
                        const float* __restrict__ W_rad) {
    __shared__ float wrad[(LMAXV + 1) * NBASIS * NMAX];
    if (threadIdx.x < (LMAXV + 1) * NBASIS * NMAX) wrad[threadIdx.x] = W_rad[threadIdx.x];
    __syncthreads();

    int e = blockIdx.x * blockDim.x + threadIdx.x;
    if (e >= N_EDGES) return;
    int s = senders[e], r = recv[e];
    int posn = g_off[r] + g_rank[e];
    float4 ps = g_pos4[s];
    float4 pr = g_pos4[r];
    float dx = pr.x - ps.x, dy = pr.y - ps.y, dz = pr.z - ps.z;
    float rn = sqrtf(dx * dx + dy * dy + dz * dz);
    float inv_u = __frcp_rn(fmaxf(rn, 1e-6f));
    float x = dx * inv_u, y = dy * inv_u, z = dz * inv_u;
    float x2 = x * x, y2 = y * y, z2 = z * z;

    float sh[16];
    sh[0]  = 0.28209479f;
    sh[1]  = 0.48860251f * y;
    sh[2]  = 0.48860251f * z;
    sh[3]  = 0.48860251f * x;
    sh[4]  = 1.09254843f * x * y;
    sh[5]  = 1.09254843f * y * z;
    sh[6]  = 0.31539157f * (3.0f * z2 - 1.0f);
    sh[7]  = 1.09254843f * x * z;
    sh[8]  = 0.54627422f * (x2 - y2);
    sh[9]  = 0.59004359f * y * (3.0f * x2 - y2);
    sh[10] = 2.89061144f * x * y * z;
    sh[11] = 0.45704579f * y * (5.0f * z2 - 1.0f);
    sh[12] = 0.37317633f * z * (5.0f * z2 - 3.0f);
    sh[13] = 0.45704579f * x * (5.0f * z2 - 1.0f);
    sh[14] = 1.44530572f * z * (x2 - y2);
    sh[15] = 0.59004359f * x * (x2 - 3.0f * y2);

    float rr = fmaxf(rn, 1e-6f);
    float theta = PI_F * (1.0f / CUTOFF) * rr;
    float s1, c1;
    sincosf(theta, &s1, &c1);
    float fc = (theta < PI_F) ? 0.5f * (c1 + 1.0f) : 0.0f;
    float pref = 0.63245553f * inv_u * fc;
    float bf[NBASIS];
    {
        float sk = s1, ck = c1;
        bf[0] = pref * sk;
#pragma unroll
        for (int n = 1; n < NBASIS; n++) {
            float sn = fmaf(sk, c1, ck * s1);
            float cn = fmaf(ck, c1, -sk * s1);
            sk = sn; ck = cn;
            bf[n] = pref * sk;
        }
    }

    float4 Rq[LMAXV + 1];
#pragma unroll
    for (int l = 0; l <= LMAXV; l++) {
        float a0 = 0.f, a1 = 0.f, a2 = 0.f, a3 = 0.f;
#pragma unroll
        for (int b = 0; b < NBASIS; b++) {
            const float* wl = &wrad[l * (NBASIS * NMAX) + b * NMAX];
            a0 = fmaf(bf[b], wl[0], a0);
            a1 = fmaf(bf[b], wl[1], a1);
            a2 = fmaf(bf[b], wl[2], a2);
            a3 = fmaf(bf[b], wl[3], a3);
        }
        Rq[l] = make_float4(a0, a1, a2, a3);
    }

    g_send[posn] = s;
    float4* SH4 = (float4*)&g_sh[(size_t)posn * 16];
    SH4[0] = make_float4(sh[0],  sh[1],  sh[2],  sh[3]);
    SH4[1] = make_float4(sh[4],  sh[5],  sh[6],  sh[7]);
    SH4[2] = make_float4(sh[8],  sh[9],  sh[10], sh[11]);
    SH4[3] = make_float4(sh[12], sh[13], sh[14], sh[15]);
    float4* R4p = (float4*)&g_R[(size_t)posn * 16];
    R4p[0] = Rq[0]; R4p[1] = Rq[1]; R4p[2] = Rq[2]; R4p[3] = Rq[3];
}

// ---------------- warp-per-atom layer: gather + CG invariants ----------------
// lane (jg = lane&15 owns j = l(jg)^2+m flat index; ch = lane>>4 owns c = 8ch..8ch+7)
// m-reduction via predicated shfl tree (no smA smem -> high occupancy).
template<bool FINAL>
__global__ void __launch_bounds__(128) k_layer(
    int use_h1,
    const float* __restrict__ W,       // W_inv1 (non-final)
    const float* __restrict__ comp_w,  // final
    const int* __restrict__ species,   // final
    const int* __restrict__ sid,       // final
    float* __restrict__ out)           // final
{
    const float* __restrict__ h_in = use_h1 ? g_h1 : g_cemb;
    int warp = threadIdx.x >> 5, lane = threadIdx.x & 31;
    int atom = (blockIdx.x << 2) + warp;
    int jg = lane & 15, ch2 = (lane >> 4) << 1;
    int l = (jg == 0) ? 0 : (jg < 4) ? 1 : (jg < 9) ? 2 : 3;

    int off = g_off[atom];
    int cnt = g_off[atom + 1] - off;

    float acc[4][8];
#pragma unroll
    for (int n = 0; n < 4; n++)
#pragma unroll
        for (int cc = 0; cc < 8; cc++) acc[n][cc] = 0.f;

    const float* shp = g_sh + (size_t)off * 16 + jg;
    const float* Rp  = g_R  + (size_t)off * 16 + 4 * l;
    const int*   sp  = g_send + off;
    const float4* h4 = (const float4*)h_in;

#define ACCROW(n, u, ha, hb) \
        acc[n][0] = fmaf(u, ha.x, acc[n][0]); acc[n][1] = fmaf(u, ha.y, acc[n][1]); \
        acc[n][2] = fmaf(u, ha.z, acc[n][2]); acc[n][3] = fmaf(u, ha.w, acc[n][3]); \
        acc[n][4] = fmaf(u, hb.x, acc[n][4]); acc[n][5] = fmaf(u, hb.y, acc[n][5]); \
        acc[n][6] = fmaf(u, hb.z, acc[n][6]); acc[n][7] = fmaf(u, hb.w, acc[n][7]);

    int s0 = (cnt > 0) ? sp[0] : 0;
    int s1 = (cnt > 1) ? sp[1] : 0;
    int k = 0;
    for (; k + 1 < cnt; k += 2) {
        float  shv0 = shp[(size_t)k * 16];
        float  shv1 = shp[(size_t)(k + 1) * 16];
        float4 R40  = *(const float4*)(Rp + (size_t)k * 16);
        float4 R41  = *(const float4*)(Rp + (size_t)(k + 1) * 16);
        float4 ha0  = h4[s0 * 4 + ch2];
        float4 hb0  = h4[s0 * 4 + ch2 + 1];
        float4 ha1  = h4[s1 * 4 + ch2];
        float4 hb1  = h4[s1 * 4 + ch2 + 1];
        if (k + 2 < cnt) s0 = sp[k + 2];
        if (k + 3 < cnt) s1 = sp[k + 3];

        float u0 = shv0 * R40.x, u1 = shv0 * R40.y, u2 = shv0 * R40.z, u3 = shv0 * R40.w;
        ACCROW(0, u0, ha0, hb0) ACCROW(1, u1, ha0, hb0)
        ACCROW(2, u2, ha0, hb0) ACCROW(3, u3, ha0, hb0)
        float v0 = shv1 * R41.x, v1 = shv1 * R41.y, v2 = shv1 * R41.z, v3 = shv1 * R41.w;
        ACCROW(0, v0, ha1, hb1) ACCROW(1, v1, ha1, hb1)
        ACCROW(2, v2, ha1, hb1) ACCROW(3, v3, ha1, hb1)
    }
    if (k < cnt) {
        float  shv = shp[(size_t)k * 16];
        float4 R4  = *(const float4*)(Rp + (size_t)k * 16);
        float4 ha  = h4[s0 * 4 + ch2];
        float4 hb  = h4[s0 * 4 + ch2 + 1];
        float u0 = shv * R4.x, u1 = shv * R4.y, u2 = shv * R4.z, u3 = shv * R4.w;
        ACCROW(0, u0, ha, hb) ACCROW(1, u1, ha, hb)
        ACCROW(2, u2, ha, hb) ACCROW(3, u3, ha, hb)
    }
#undef ACCROW

    if (FINAL) {
        // fold w' into A^2 directly: e = sum_{j,c} A[j,c]^2 * w'[l,n,c]; all in registers
        const float* wp = g_wp + l * 64 + 4 * ch2;   // + n*16 + cc
        float part = 0.f;
#pragma unroll
        for (int n = 0; n < 4; n++) {
            const float* wn = wp + n * 16;
#pragma unroll
            for (int cc = 0; cc < 8; cc++) {
                float a = acc[n][cc];
                part = fmaf(a * a, wn[cc], part);
            }
        }
#pragma unroll
        for (int o = 16; o > 0; o >>= 1)
            part += __shfl_down_sync(0xFFFFFFFFu, part, o);
        if (lane == 0)
            atomicAdd(&out[sid[atom]], part + comp_w[species[atom]]);
    } else {
        __shared__ float sminv[4][KTOT];   // only 4KB total now

        // square in place
#pragma unroll
        for (int n = 0; n < 4; n++)
#pragma unroll
            for (int cc = 0; cc < 8; cc++)
                acc[n][cc] *= acc[n][cc];

        // predicated shfl tree over the m-group (contiguous jg lanes within each half)
        // o = jg - l*l in [0, 2l]; step d folds lane o+d's segment [o+d, o+2d-1]
        int o = jg - l * l;
        int span = 2 * l;
#pragma unroll
        for (int d = 1; d <= 4; d <<= 1) {
            bool take = (o + d) <= span;
#pragma unroll
            for (int n = 0; n < 4; n++)
#pragma unroll
                for (int cc = 0; cc < 8; cc++) {
                    float t = __shfl_down_sync(0xFFFFFFFFu, acc[n][cc], d);
                    if (take) acc[n][cc] += t;
                }
        }

        // group leaders (o == 0) hold inv tiles; scale and publish to smem
        float* sv = sminv[warp];
        if (o == 0) {
            float sc = rsqrtf(2.0f * (float)l + 1.0f);
            int base = l * 64 + 4 * ch2;   // + n*16 + cc
#pragma unroll
            for (int n = 0; n < 4; n++)
#pragma unroll
                for (int cc = 0; cc < 8; cc++)
                    sv[base + n * 16 + cc] = acc[n][cc] * sc;
        }
        __syncwarp();

        int cp = lane & 15, half = lane >> 4;
        float p0 = 0.f, p1 = 0.f;
#pragma unroll 8
        for (int i = 0; i < 128; i += 2) {
            int jj = (half << 7) + i;
            p0 = fmaf(sv[jj],     W[jj * 16 + cp],       p0);
            p1 = fmaf(sv[jj + 1], W[(jj + 1) * 16 + cp], p1);
        }
        float p = p0 + p1;
        p += __shfl_down_sync(0xFFFFFFFFu, p, 16);
        if (lane < 16)
            g_h1[atom * CH + lane] = p * g_cemb[atom * CH + lane];
    }
}

// ---------------- launch ----------------
extern "C" void kernel_launch(void* const* d_in, const int* in_sizes, int n_in,
                              void* d_out, int out_size) {
    const float* positions  = (const float*)d_in[0];
    const float* embed      = (const float*)d_in[1];
    const float* W_rad      = (const float*)d_in[2];
    const float* W_inv1     = (const float*)d_in[3];
    // d_in[4] = W_inv2 is dead: reference returns inv2 before applying it
    const float* w_out      = (const float*)d_in[5];
    const float* comp_w     = (const float*)d_in[6];
    const int*   senders    = (const int*)d_in[7];
    const int*   receivers  = (const int*)d_in[8];
    const int*   species    = (const int*)d_in[9];
    const int*   struct_ids = (const int*)d_in[10];
    float* out = (float*)d_out;

    k_prep<<<(N_EDGES + 255) / 256, 256>>>(embed, species, positions, w_out, receivers, out);
    k_scan<<<1, 1024>>>();
    k_edges<<<(N_EDGES + 255) / 256, 256>>>(senders, receivers, W_rad);

    k_layer<false><<<N_ATOMS / 4, 128>>>(0, W_inv1, nullptr, nullptr, nullptr, nullptr);
    k_layer<true><<<N_ATOMS / 4, 128>>>(1, nullptr, comp_w, species, struct_ids, out);
}